// round 13
// baseline (speedup 1.0000x reference)
#include <cuda_runtime.h>

#define BB 64
#define NN 65536
#define RADIUS 0.2f

// Scratch (__device__ globals per allocation-free rule)
__device__ float    g_x[(size_t)BB * NN];           // SoA packed xyz, 3x16 MB
__device__ float    g_y[(size_t)BB * NN];
__device__ float    g_z[(size_t)BB * NN];
__device__ float    g_pval[3][BB * 64];             // argmax partials per FPS step
__device__ int      g_pidx[3][BB * 64];
__device__ unsigned g_state[BB * 64];               // chunk count + ready flag
__device__ int      g_numvalid[BB];

// ---------------------------------------------------------------------------
// Argmax helpers: larger value wins, tie -> smaller index (jnp.argmax semantics)
// ---------------------------------------------------------------------------
__device__ __forceinline__ void warp_argmax(float& v, int& i) {
    #pragma unroll
    for (int off = 16; off; off >>= 1) {
        float ov = __shfl_down_sync(0xffffffffu, v, off);
        int   oi = __shfl_down_sync(0xffffffffu, i, off);
        if (ov > v || (ov == v && oi < i)) { v = ov; i = oi; }
    }
}

// 256-thread (8-warp) block argmax; result valid in thread 0.
__device__ __forceinline__ void block_argmax256(float& v, int& i, int tid,
                                                float* s_val, int* s_idx) {
    warp_argmax(v, i);
    if ((tid & 31) == 0) { s_val[tid >> 5] = v; s_idx[tid >> 5] = i; }
    __syncthreads();
    if (tid < 32) {
        v = (tid < 8) ? s_val[tid] : -2.0f;
        i = (tid < 8) ? s_idx[tid] : NN;
        warp_argmax(v, i);
    }
}

// Reduce 64 partials of set j -> argmax (lane 0 of calling warp holds result).
__device__ __forceinline__ void reduce_partials(int j, int b, int lane,
                                                float& v, int& i) {
    v = g_pval[j][b * 64 + lane];
    i = g_pidx[j][b * 64 + lane];
    float v2 = g_pval[j][b * 64 + 32 + lane];
    int   i2 = g_pidx[j][b * 64 + 32 + lane];
    if (v2 > v || (v2 == v && i2 < i)) { v = v2; i = i2; }
    warp_argmax(v, i);
}

// Recover centers 1..S-1 from partial sets (center 0 = point 0 of batch).
template <int S>
__device__ __forceinline__ void recover_centers(const float* __restrict__ pts,
                                                int b, int tid, float3* sc) {
    const size_t bb = (size_t)b * NN;
    if (tid == 0) {
        const float* q = pts + bb * 6;
        sc[0] = make_float3(q[0], q[1], q[2]);
    }
    if (tid < 32) {
        #pragma unroll
        for (int j = 0; j < S - 1; j++) {
            float v; int i;
            reduce_partials(j, b, tid, v, i);
            if (tid == 0) sc[j + 1] = make_float3(g_x[bb + i], g_y[bb + i], g_z[bb + i]);
        }
    }
    __syncthreads();
}

// ---------------------------------------------------------------------------
// K1: read raw pts, write SoA xyz, dist-to-center0 argmax partials.
// Also zeroes g_state for this run (visible to K4 via kernel boundaries).
// grid (64, BB) x 256; 1024 pts/block.
// ---------------------------------------------------------------------------
__global__ void __launch_bounds__(256) sweep1_pack_kernel(const float* __restrict__ pts) {
    const int b = blockIdx.y, chunk = blockIdx.x, tid = threadIdx.x;
    const float* __restrict__ base = pts + (size_t)b * NN * 6;
    const float cx = __ldg(base), cy = __ldg(base + 1), cz = __ldg(base + 2);
    const size_t bb = (size_t)b * NN;

    __shared__ float s_val[8];
    __shared__ int   s_idx[8];

    if (chunk == 0 && tid < 64) g_state[b * 64 + tid] = 0u;

    const int p0 = chunk * 1024;
    float qx[4], qy[4], qz[4];
    #pragma unroll
    for (int k = 0; k < 4; k++) {
        const float* q = base + (size_t)(p0 + k * 256 + tid) * 6;
        float2 xy = *(const float2*)q;
        qx[k] = xy.x; qy[k] = xy.y; qz[k] = q[2];
    }
    float best = -1.0f;
    int bidx = NN;
    #pragma unroll
    for (int k = 0; k < 4; k++) {
        int p = p0 + k * 256 + tid;
        g_x[bb + p] = qx[k];
        g_y[bb + p] = qy[k];
        g_z[bb + p] = qz[k];
        float dx = qx[k] - cx, dy = qy[k] - cy, dz = qz[k] - cz;
        float d = dx * dx + dy * dy + dz * dz;
        if (d > best || (d == best && p < bidx)) { best = d; bidx = p; }
    }
    block_argmax256(best, bidx, tid, s_val, s_idx);
    if (tid == 0) {
        g_pval[0][b * 64 + chunk] = best;
        g_pidx[0][b * 64 + chunk] = bidx;
    }
}

// ---------------------------------------------------------------------------
// K2/K3: FPS sweep with S known centers (S=2,3) reading SoA, batched loads.
// grid (64, BB) x 256; 1024 pts/block.
// ---------------------------------------------------------------------------
template <int S>
__global__ void __launch_bounds__(256) sweep_kernel(const float* __restrict__ pts) {
    const int b = blockIdx.y, chunk = blockIdx.x, tid = threadIdx.x;
    const size_t bb = (size_t)b * NN;
    __shared__ float3 sc[S];
    __shared__ float s_val[8];
    __shared__ int   s_idx[8];

    recover_centers<S>(pts, b, tid, sc);

    const int p0 = chunk * 1024;
    float qx[4], qy[4], qz[4];
    #pragma unroll
    for (int k = 0; k < 4; k++) {
        size_t idx = bb + p0 + k * 256 + tid;
        qx[k] = g_x[idx]; qy[k] = g_y[idx]; qz[k] = g_z[idx];
    }
    float best = -1.0f;
    int bidx = NN;
    #pragma unroll
    for (int k = 0; k < 4; k++) {
        int p = p0 + k * 256 + tid;
        float m = 1e10f;
        #pragma unroll
        for (int t = 0; t < S; t++) {
            float dx = qx[k] - sc[t].x, dy = qy[k] - sc[t].y, dz = qz[k] - sc[t].z;
            float d = dx * dx + dy * dy + dz * dz;
            m = fminf(m, d);
        }
        if (m > best || (m == best && p < bidx)) { best = m; bidx = p; }
    }
    block_argmax256(best, bidx, tid, s_val, s_idx);
    if (tid == 0) {
        g_pval[S - 1][b * 64 + chunk] = best;
        g_pidx[S - 1][b * 64 + chunk] = bidx;
    }
}

// ---------------------------------------------------------------------------
// K4: FUSED keep + stable scatter. grid (64, BB) x 256; 1024 pts/block.
// Computes keep from the pts rows it must load anyway, publishes its chunk
// count, sums predecessor counts (spin on L2-coherent flags), scatters.
// ---------------------------------------------------------------------------
__global__ void __launch_bounds__(256) scatter_fused_kernel(const float* __restrict__ pts,
                                                            float* __restrict__ out) {
    const int b = blockIdx.y, chunk = blockIdx.x, tid = threadIdx.x;
    const int lane = tid & 31, warp = tid >> 5;
    __shared__ float3 sc[4];
    __shared__ unsigned s_w[32];
    __shared__ int s_wpref[32];
    __shared__ int s_excl;

    recover_centers<4>(pts, b, tid, sc);

    const float* __restrict__ base = pts + (size_t)b * NN * 6;
    float* __restrict__ obase = out + (size_t)b * NN * 6;
    const int p0 = chunk * 1024;

    // batched unconditional loads of this block's 4 rows (12 independent LDGs)
    float2 r[4][3];
    #pragma unroll
    for (int k = 0; k < 4; k++) {
        const float2* s = (const float2*)(base + (size_t)(p0 + k * 256 + tid) * 6);
        r[k][0] = s[0]; r[k][1] = s[1]; r[k][2] = s[2];
    }

    // keep predicate straight from the loaded rows
    #pragma unroll
    for (int k = 0; k < 4; k++) {
        float qx = r[k][0].x, qy = r[k][0].y, qz = r[k][1].x;
        float m = 1e10f;
        #pragma unroll
        for (int t = 0; t < 4; t++) {
            float dx = qx - sc[t].x, dy = qy - sc[t].y, dz = qz - sc[t].z;
            float d = dx * dx + dy * dy + dz * dz;
            m = fminf(m, d);
        }
        bool keep = (sqrtf(m) >= RADIUS);   // == (norm >= 0.2), sqrt monotone
        unsigned w = __ballot_sync(0xffffffffu, keep);
        if (lane == 0) s_w[k * 8 + warp] = w;
    }
    __syncthreads();

    // warp 0: prefix over 32 words; publish block total; lookback-sum predecessors
    if (tid < 32) {
        int pc = __popc(s_w[tid]);
        int inc = pc;
        #pragma unroll
        for (int off = 1; off < 32; off <<= 1) {
            int n = __shfl_up_sync(0xffffffffu, inc, off);
            if (tid >= off) inc += n;
        }
        s_wpref[tid] = inc - pc;
        if (tid == 31)
            atomicExch(&g_state[b * 64 + chunk], 0x40000000u | (unsigned)inc);

        // sum all predecessor chunk counts (spin until each is published)
        int sum = 0;
        #pragma unroll
        for (int w = 0; w < 2; w++) {
            int idx = w * 32 + tid;
            if (idx < chunk) {
                volatile unsigned* p = &g_state[b * 64 + idx];
                unsigned s;
                do { s = *p; } while (!(s & 0x40000000u));
                sum += (int)(s & 0x3FFFFFFFu);
            }
        }
        #pragma unroll
        for (int off = 16; off; off >>= 1) sum += __shfl_down_sync(0xffffffffu, sum, off);
        if (tid == 0) s_excl = sum;
    }
    __syncthreads();

    const int excl = s_excl;
    if (chunk == 63 && tid == 0)
        g_numvalid[b] = excl + s_wpref[31] + __popc(s_w[31]);

    #pragma unroll
    for (int k = 0; k < 4; k++) {
        int pl = k * 256 + tid;                 // local point 0..1023
        unsigned word = s_w[pl >> 5];
        int bit = pl & 31;
        if ((word >> bit) & 1u) {
            int rank = excl + s_wpref[pl >> 5] + __popc(word & ((1u << bit) - 1u));
            float2* o = (float2*)(obase + (size_t)rank * 6);
            o[0] = r[k][0]; o[1] = r[k][1]; o[2] = r[k][2];
        }
    }
}

// ---------------------------------------------------------------------------
// K5: tail fill: rows j >= nv copy from out[j % nv]; nv==0 -> zeros.
// Source rows were written by K4 (previous kernel) — no hazard.
// ---------------------------------------------------------------------------
__global__ void __launch_bounds__(256) tail_kernel(float* __restrict__ out) {
    int i = blockIdx.x * blockDim.x + threadIdx.x;
    if (i >= BB * NN) return;
    int b = i >> 16;
    int j = i & (NN - 1);
    int nv = g_numvalid[b];
    float* __restrict__ obase = out + (size_t)b * NN * 6;
    if (nv == 0) {
        float2 z = make_float2(0.f, 0.f);
        float2* o = (float2*)(obase + (size_t)j * 6);
        o[0] = z; o[1] = z; o[2] = z;
        return;
    }
    if (j < nv) return;
    int k = j % nv;
    const float2* s = (const float2*)(obase + (size_t)k * 6);
    float2 a0 = s[0], a1 = s[1], a2 = s[2];
    float2* o = (float2*)(obase + (size_t)j * 6);
    o[0] = a0; o[1] = a1; o[2] = a2;
}

extern "C" void kernel_launch(void* const* d_in, const int* in_sizes, int n_in,
                              void* d_out, int out_size) {
    const float* pts = (const float*)d_in[0];
    float* out = (float*)d_out;
    (void)in_sizes; (void)n_in; (void)out_size;

    sweep1_pack_kernel<<<dim3(64, BB), 256>>>(pts);
    sweep_kernel<2><<<dim3(64, BB), 256>>>(pts);
    sweep_kernel<3><<<dim3(64, BB), 256>>>(pts);
    scatter_fused_kernel<<<dim3(64, BB), 256>>>(pts, out);
    tail_kernel<<<(BB * NN + 255) / 256, 256>>>(out);
}

// round 14
// speedup vs baseline: 1.0276x; 1.0276x over previous
#include <cuda_runtime.h>

#define BB 64
#define NN 65536
#define RADIUS 0.2f

// Scratch (__device__ globals per allocation-free rule)
__device__ float    g_x[(size_t)BB * NN];           // SoA packed xyz, 3x16 MB
__device__ float    g_y[(size_t)BB * NN];
__device__ float    g_z[(size_t)BB * NN];
__device__ float    g_pval[3][BB * 64];             // argmax partials per FPS step
__device__ int      g_pidx[3][BB * 64];
__device__ unsigned g_bm[BB * (NN / 32)];           // keep bitmask, 512 KB
__device__ int      g_cnt[BB * 64];                 // per-chunk keep counts
__device__ int      g_numvalid[BB];

// ---------------------------------------------------------------------------
// Argmax helpers: larger value wins, tie -> smaller index (jnp.argmax semantics)
// ---------------------------------------------------------------------------
__device__ __forceinline__ void warp_argmax(float& v, int& i) {
    #pragma unroll
    for (int off = 16; off; off >>= 1) {
        float ov = __shfl_down_sync(0xffffffffu, v, off);
        int   oi = __shfl_down_sync(0xffffffffu, i, off);
        if (ov > v || (ov == v && oi < i)) { v = ov; i = oi; }
    }
}

// 256-thread (8-warp) block argmax; result valid in thread 0.
__device__ __forceinline__ void block_argmax256(float& v, int& i, int tid,
                                                float* s_val, int* s_idx) {
    warp_argmax(v, i);
    if ((tid & 31) == 0) { s_val[tid >> 5] = v; s_idx[tid >> 5] = i; }
    __syncthreads();
    if (tid < 32) {
        v = (tid < 8) ? s_val[tid] : -2.0f;
        i = (tid < 8) ? s_idx[tid] : NN;
        warp_argmax(v, i);
    }
}

// Reduce 64 partials of set j -> argmax (lane 0 of calling warp holds result).
__device__ __forceinline__ void reduce_partials(int j, int b, int lane,
                                                float& v, int& i) {
    v = g_pval[j][b * 64 + lane];
    i = g_pidx[j][b * 64 + lane];
    float v2 = g_pval[j][b * 64 + 32 + lane];
    int   i2 = g_pidx[j][b * 64 + 32 + lane];
    if (v2 > v || (v2 == v && i2 < i)) { v = v2; i = i2; }
    warp_argmax(v, i);
}

// Recover centers 1..S-1 from partial sets (center 0 = point 0 of batch).
template <int S>
__device__ __forceinline__ void recover_centers(const float* __restrict__ pts,
                                                int b, int tid, float3* sc) {
    const size_t bb = (size_t)b * NN;
    if (tid == 0) {
        const float* q = pts + bb * 6;
        sc[0] = make_float3(q[0], q[1], q[2]);
    }
    if (tid < 32) {
        #pragma unroll
        for (int j = 0; j < S - 1; j++) {
            float v; int i;
            reduce_partials(j, b, tid, v, i);
            if (tid == 0) sc[j + 1] = make_float3(g_x[bb + i], g_y[bb + i], g_z[bb + i]);
        }
    }
    __syncthreads();
}

// ---------------------------------------------------------------------------
// K1: read raw pts, write SoA xyz, dist-to-center0 argmax partials.
// grid (64, BB) x 256; 1024 pts/block. Loads batched up front.
// ---------------------------------------------------------------------------
__global__ void __launch_bounds__(256) sweep1_pack_kernel(const float* __restrict__ pts) {
    const int b = blockIdx.y, chunk = blockIdx.x, tid = threadIdx.x;
    const float* __restrict__ base = pts + (size_t)b * NN * 6;
    const float cx = __ldg(base), cy = __ldg(base + 1), cz = __ldg(base + 2);
    const size_t bb = (size_t)b * NN;

    __shared__ float s_val[8];
    __shared__ int   s_idx[8];

    const int p0 = chunk * 1024;
    float qx[4], qy[4], qz[4];
    #pragma unroll
    for (int k = 0; k < 4; k++) {
        const float* q = base + (size_t)(p0 + k * 256 + tid) * 6;
        float2 xy = *(const float2*)q;
        qx[k] = xy.x; qy[k] = xy.y; qz[k] = q[2];
    }
    float best = -1.0f;
    int bidx = NN;
    #pragma unroll
    for (int k = 0; k < 4; k++) {
        int p = p0 + k * 256 + tid;
        g_x[bb + p] = qx[k];
        g_y[bb + p] = qy[k];
        g_z[bb + p] = qz[k];
        float dx = qx[k] - cx, dy = qy[k] - cy, dz = qz[k] - cz;
        float d = dx * dx + dy * dy + dz * dz;
        if (d > best || (d == best && p < bidx)) { best = d; bidx = p; }
    }
    block_argmax256(best, bidx, tid, s_val, s_idx);
    if (tid == 0) {
        g_pval[0][b * 64 + chunk] = best;
        g_pidx[0][b * 64 + chunk] = bidx;
    }
}

// ---------------------------------------------------------------------------
// K2/K3: FPS sweep with S known centers (S=2,3) reading SoA, batched loads.
// grid (64, BB) x 256; 1024 pts/block.
// ---------------------------------------------------------------------------
template <int S>
__global__ void __launch_bounds__(256) sweep_kernel(const float* __restrict__ pts) {
    const int b = blockIdx.y, chunk = blockIdx.x, tid = threadIdx.x;
    const size_t bb = (size_t)b * NN;
    __shared__ float3 sc[S];
    __shared__ float s_val[8];
    __shared__ int   s_idx[8];

    recover_centers<S>(pts, b, tid, sc);

    const int p0 = chunk * 1024;
    float qx[4], qy[4], qz[4];
    #pragma unroll
    for (int k = 0; k < 4; k++) {
        size_t idx = bb + p0 + k * 256 + tid;
        qx[k] = g_x[idx]; qy[k] = g_y[idx]; qz[k] = g_z[idx];
    }
    float best = -1.0f;
    int bidx = NN;
    #pragma unroll
    for (int k = 0; k < 4; k++) {
        int p = p0 + k * 256 + tid;
        float m = 1e10f;
        #pragma unroll
        for (int t = 0; t < S; t++) {
            float dx = qx[k] - sc[t].x, dy = qy[k] - sc[t].y, dz = qz[k] - sc[t].z;
            float d = dx * dx + dy * dy + dz * dz;
            m = fminf(m, d);
        }
        if (m > best || (m == best && p < bidx)) { best = m; bidx = p; }
    }
    block_argmax256(best, bidx, tid, s_val, s_idx);
    if (tid == 0) {
        g_pval[S - 1][b * 64 + chunk] = best;
        g_pidx[S - 1][b * 64 + chunk] = bidx;
    }
}

// ---------------------------------------------------------------------------
// K4: keep test against 4 centers -> bitmask + per-chunk counts.
// grid (64, BB) x 256; 1024 pts/block, batch 4 SoA loads (low regs, high occ).
// ---------------------------------------------------------------------------
__global__ void __launch_bounds__(256) keep_kernel(const float* __restrict__ pts) {
    const int b = blockIdx.y, chunk = blockIdx.x, tid = threadIdx.x;
    const size_t bb = (size_t)b * NN;
    __shared__ float3 sc[4];
    __shared__ int s_c[8];

    recover_centers<4>(pts, b, tid, sc);

    const int lane = tid & 31, warp = tid >> 5;
    const int p0 = chunk * 1024;

    float qx[4], qy[4], qz[4];
    #pragma unroll
    for (int k = 0; k < 4; k++) {
        size_t idx = bb + p0 + k * 256 + tid;
        qx[k] = g_x[idx]; qy[k] = g_y[idx]; qz[k] = g_z[idx];
    }

    int cnt = 0;
    #pragma unroll
    for (int k = 0; k < 4; k++) {
        int p = p0 + k * 256 + tid;
        float m = 1e10f;
        #pragma unroll
        for (int t = 0; t < 4; t++) {
            float dx = qx[k] - sc[t].x, dy = qy[k] - sc[t].y, dz = qz[k] - sc[t].z;
            float d = dx * dx + dy * dy + dz * dz;
            m = fminf(m, d);
        }
        bool keep = (sqrtf(m) >= RADIUS);   // == (norm >= 0.2), sqrt monotone
        unsigned w = __ballot_sync(0xffffffffu, keep);
        if (lane == 0) g_bm[b * (NN / 32) + (p >> 5)] = w;
        cnt += keep;
    }
    #pragma unroll
    for (int off = 16; off; off >>= 1) cnt += __shfl_down_sync(0xffffffffu, cnt, off);
    if (lane == 0) s_c[warp] = cnt;
    __syncthreads();
    if (tid == 0) {
        int tot = 0;
        #pragma unroll
        for (int i = 0; i < 8; i++) tot += s_c[i];
        g_cnt[b * 64 + chunk] = tot;
    }
}

// ---------------------------------------------------------------------------
// K5: scatter kept points to out[rank]. grid (64, BB) x 256; 1024 pts/block.
// Chunk offset = sum of predecessor counts (2 L2 loads + warp reduce, no spin).
// ---------------------------------------------------------------------------
__global__ void __launch_bounds__(256) scatter_kernel(const float* __restrict__ pts,
                                                      float* __restrict__ out) {
    const int b = blockIdx.y, chunk = blockIdx.x, tid = threadIdx.x;
    __shared__ unsigned s_w[32];
    __shared__ int s_wpref[32];
    __shared__ int s_excl;

    // warp 1: load this chunk's 32 bitmask words
    if (tid >= 32 && tid < 64)
        s_w[tid - 32] = g_bm[b * (NN / 32) + chunk * 32 + (tid - 32)];

    // warp 0: predecessor-count sum + numvalid (from chunk 0)
    if (tid < 32) {
        int c0 = g_cnt[b * 64 + tid];
        int c1 = g_cnt[b * 64 + 32 + tid];
        int sum = (tid < chunk ? c0 : 0) + (32 + tid < chunk ? c1 : 0);
        int tot = c0 + c1;
        #pragma unroll
        for (int off = 16; off; off >>= 1) {
            sum += __shfl_down_sync(0xffffffffu, sum, off);
            tot += __shfl_down_sync(0xffffffffu, tot, off);
        }
        if (tid == 0) {
            s_excl = sum;
            if (chunk == 0) g_numvalid[b] = tot;
        }
    }
    __syncthreads();

    // warp 0: exclusive word-prefix over 32 popcounts
    if (tid < 32) {
        int pc = __popc(s_w[tid]);
        int inc = pc;
        #pragma unroll
        for (int off = 1; off < 32; off <<= 1) {
            int n = __shfl_up_sync(0xffffffffu, inc, off);
            if (tid >= off) inc += n;
        }
        s_wpref[tid] = inc - pc;
    }
    __syncthreads();

    const float* __restrict__ base = pts + (size_t)b * NN * 6;
    float* __restrict__ obase = out + (size_t)b * NN * 6;
    const int p0 = chunk * 1024;
    const int excl = s_excl;

    // batched unconditional loads of 4 rows (12 independent float2 LDGs)
    float2 r[4][3];
    #pragma unroll
    for (int k = 0; k < 4; k++) {
        const float2* s = (const float2*)(base + (size_t)(p0 + k * 256 + tid) * 6);
        r[k][0] = s[0]; r[k][1] = s[1]; r[k][2] = s[2];
    }
    #pragma unroll
    for (int k = 0; k < 4; k++) {
        int pl = k * 256 + tid;                 // local point 0..1023
        unsigned word = s_w[pl >> 5];
        int bit = pl & 31;
        if ((word >> bit) & 1u) {
            int rank = excl + s_wpref[pl >> 5] + __popc(word & ((1u << bit) - 1u));
            float2* o = (float2*)(obase + (size_t)rank * 6);
            o[0] = r[k][0]; o[1] = r[k][1]; o[2] = r[k][2];
        }
    }
}

// ---------------------------------------------------------------------------
// K6: tail fill: rows j >= nv copy from out[j % nv]; nv==0 -> zeros.
// Source rows were written by K5 (previous kernel) — no hazard.
// ---------------------------------------------------------------------------
__global__ void __launch_bounds__(256) tail_kernel(float* __restrict__ out) {
    int i = blockIdx.x * blockDim.x + threadIdx.x;
    if (i >= BB * NN) return;
    int b = i >> 16;
    int j = i & (NN - 1);
    int nv = g_numvalid[b];
    float* __restrict__ obase = out + (size_t)b * NN * 6;
    if (nv == 0) {
        float2 z = make_float2(0.f, 0.f);
        float2* o = (float2*)(obase + (size_t)j * 6);
        o[0] = z; o[1] = z; o[2] = z;
        return;
    }
    if (j < nv) return;
    int k = j % nv;
    const float2* s = (const float2*)(obase + (size_t)k * 6);
    float2 a0 = s[0], a1 = s[1], a2 = s[2];
    float2* o = (float2*)(obase + (size_t)j * 6);
    o[0] = a0; o[1] = a1; o[2] = a2;
}

extern "C" void kernel_launch(void* const* d_in, const int* in_sizes, int n_in,
                              void* d_out, int out_size) {
    const float* pts = (const float*)d_in[0];
    float* out = (float*)d_out;
    (void)in_sizes; (void)n_in; (void)out_size;

    sweep1_pack_kernel<<<dim3(64, BB), 256>>>(pts);
    sweep_kernel<2><<<dim3(64, BB), 256>>>(pts);
    sweep_kernel<3><<<dim3(64, BB), 256>>>(pts);
    keep_kernel<<<dim3(64, BB), 256>>>(pts);
    scatter_kernel<<<dim3(64, BB), 256>>>(pts, out);
    tail_kernel<<<(BB * NN + 255) / 256, 256>>>(out);
}

// round 15
// speedup vs baseline: 1.1241x; 1.0939x over previous
#include <cuda_runtime.h>

#define BB 64
#define NN 65536
#define RADIUS 0.2f

// Scratch (__device__ globals per allocation-free rule)
__device__ float    g_x[(size_t)BB * NN];           // SoA packed xyz, 3x16 MB
__device__ float    g_y[(size_t)BB * NN];
__device__ float    g_z[(size_t)BB * NN];
__device__ float    g_pval[3][BB * 64];             // argmax partials per FPS step
__device__ int      g_pidx[3][BB * 64];
__device__ float4   g_ctr[BB * 4];                  // finalized centers
__device__ unsigned g_bm[BB * (NN / 32)];           // keep bitmask, 512 KB
__device__ int      g_cnt[BB * 32];                 // per-chunk keep counts
__device__ int      g_numvalid[BB];

// ---------------------------------------------------------------------------
// Argmax helpers: larger value wins, tie -> smaller index (jnp.argmax semantics)
// ---------------------------------------------------------------------------
__device__ __forceinline__ void warp_argmax(float& v, int& i) {
    #pragma unroll
    for (int off = 16; off; off >>= 1) {
        float ov = __shfl_down_sync(0xffffffffu, v, off);
        int   oi = __shfl_down_sync(0xffffffffu, i, off);
        if (ov > v || (ov == v && oi < i)) { v = ov; i = oi; }
    }
}

// 256-thread (8-warp) block argmax; result valid in thread 0.
__device__ __forceinline__ void block_argmax256(float& v, int& i, int tid,
                                                float* s_val, int* s_idx) {
    warp_argmax(v, i);
    if ((tid & 31) == 0) { s_val[tid >> 5] = v; s_idx[tid >> 5] = i; }
    __syncthreads();
    if (tid < 32) {
        v = (tid < 8) ? s_val[tid] : -2.0f;
        i = (tid < 8) ? s_idx[tid] : NN;
        warp_argmax(v, i);
    }
}

// Reduce 64 partials of set j -> argmax (lane 0 of calling warp holds result).
__device__ __forceinline__ void reduce_partials(int j, int b, int lane,
                                                float& v, int& i) {
    v = g_pval[j][b * 64 + lane];
    i = g_pidx[j][b * 64 + lane];
    float v2 = g_pval[j][b * 64 + 32 + lane];
    int   i2 = g_pidx[j][b * 64 + 32 + lane];
    if (v2 > v || (v2 == v && i2 < i)) { v = v2; i = i2; }
    warp_argmax(v, i);
}

// Recover centers 1..S-1 from partial sets (center 0 = point 0 of batch).
template <int S>
__device__ __forceinline__ void recover_centers(const float* __restrict__ pts,
                                                int b, int tid, float3* sc) {
    const size_t bb = (size_t)b * NN;
    if (tid == 0) {
        const float* q = pts + bb * 6;
        sc[0] = make_float3(q[0], q[1], q[2]);
    }
    if (tid < 32) {
        #pragma unroll
        for (int j = 0; j < S - 1; j++) {
            float v; int i;
            reduce_partials(j, b, tid, v, i);
            if (tid == 0) sc[j + 1] = make_float3(g_x[bb + i], g_y[bb + i], g_z[bb + i]);
        }
    }
    __syncthreads();
}

// ---------------------------------------------------------------------------
// K1: read raw pts, write SoA xyz, dist-to-center0 argmax partials.
// grid (64, BB) x 256; 1024 pts/block. Loads batched up front.
// ---------------------------------------------------------------------------
__global__ void __launch_bounds__(256) sweep1_pack_kernel(const float* __restrict__ pts) {
    const int b = blockIdx.y, chunk = blockIdx.x, tid = threadIdx.x;
    const float* __restrict__ base = pts + (size_t)b * NN * 6;
    const float cx = __ldg(base), cy = __ldg(base + 1), cz = __ldg(base + 2);
    const size_t bb = (size_t)b * NN;

    __shared__ float s_val[8];
    __shared__ int   s_idx[8];

    const int p0 = chunk * 1024;
    float qx[4], qy[4], qz[4];
    #pragma unroll
    for (int k = 0; k < 4; k++) {
        const float* q = base + (size_t)(p0 + k * 256 + tid) * 6;
        float2 xy = *(const float2*)q;
        qx[k] = xy.x; qy[k] = xy.y; qz[k] = q[2];
    }
    float best = -1.0f;
    int bidx = NN;
    #pragma unroll
    for (int k = 0; k < 4; k++) {
        int p = p0 + k * 256 + tid;
        g_x[bb + p] = qx[k];
        g_y[bb + p] = qy[k];
        g_z[bb + p] = qz[k];
        float dx = qx[k] - cx, dy = qy[k] - cy, dz = qz[k] - cz;
        float d = dx * dx + dy * dy + dz * dz;
        if (d > best || (d == best && p < bidx)) { best = d; bidx = p; }
    }
    block_argmax256(best, bidx, tid, s_val, s_idx);
    if (tid == 0) {
        g_pval[0][b * 64 + chunk] = best;
        g_pidx[0][b * 64 + chunk] = bidx;
    }
}

// ---------------------------------------------------------------------------
// K2/K3: FPS sweep with S known centers (S=2,3) reading SoA, batched loads.
// grid (64, BB) x 256; 1024 pts/block.
// ---------------------------------------------------------------------------
template <int S>
__global__ void __launch_bounds__(256) sweep_kernel(const float* __restrict__ pts) {
    const int b = blockIdx.y, chunk = blockIdx.x, tid = threadIdx.x;
    const size_t bb = (size_t)b * NN;
    __shared__ float3 sc[S];
    __shared__ float s_val[8];
    __shared__ int   s_idx[8];

    recover_centers<S>(pts, b, tid, sc);

    const int p0 = chunk * 1024;
    float qx[4], qy[4], qz[4];
    #pragma unroll
    for (int k = 0; k < 4; k++) {
        size_t idx = bb + p0 + k * 256 + tid;
        qx[k] = g_x[idx]; qy[k] = g_y[idx]; qz[k] = g_z[idx];
    }
    float best = -1.0f;
    int bidx = NN;
    #pragma unroll
    for (int k = 0; k < 4; k++) {
        int p = p0 + k * 256 + tid;
        float m = 1e10f;
        #pragma unroll
        for (int t = 0; t < S; t++) {
            float dx = qx[k] - sc[t].x, dy = qy[k] - sc[t].y, dz = qz[k] - sc[t].z;
            float d = dx * dx + dy * dy + dz * dz;
            m = fminf(m, d);
        }
        if (m > best || (m == best && p < bidx)) { best = m; bidx = p; }
    }
    block_argmax256(best, bidx, tid, s_val, s_idx);
    if (tid == 0) {
        g_pval[S - 1][b * 64 + chunk] = best;
        g_pidx[S - 1][b * 64 + chunk] = bidx;
    }
}

// ---------------------------------------------------------------------------
// K4: finalize all 4 centers per batch (single reduction pass). grid BB x 32.
// ---------------------------------------------------------------------------
__global__ void __launch_bounds__(32) finalize_kernel(const float* __restrict__ pts) {
    const int b = blockIdx.x, lane = threadIdx.x;
    const size_t bb = (size_t)b * NN;
    if (lane == 0) {
        const float* q = pts + bb * 6;
        g_ctr[b * 4] = make_float4(q[0], q[1], q[2], 0.0f);
    }
    #pragma unroll
    for (int j = 0; j < 3; j++) {
        float v; int i;
        reduce_partials(j, b, lane, v, i);
        if (lane == 0)
            g_ctr[b * 4 + j + 1] = make_float4(g_x[bb + i], g_y[bb + i], g_z[bb + i], 0.0f);
    }
}

// ---------------------------------------------------------------------------
// K5: keep test against 4 centers -> bitmask + per-chunk counts.
// grid (32, BB) x 256; 2048 pts/block, batch 8 (measured-best MLP config).
// Centers loaded directly from g_ctr — no per-block reduction preamble.
// ---------------------------------------------------------------------------
__global__ void __launch_bounds__(256) keep_kernel() {
    const int b = blockIdx.y, chunk = blockIdx.x, tid = threadIdx.x;
    const size_t bb = (size_t)b * NN;
    __shared__ float3 sc[4];
    __shared__ int s_c[8];

    if (tid < 4) {
        float4 c = g_ctr[b * 4 + tid];
        sc[tid] = make_float3(c.x, c.y, c.z);
    }
    __syncthreads();

    const int lane = tid & 31, warp = tid >> 5;
    const int p0 = chunk * 2048;

    // phase 1: 24 independent loads -> high MLP
    float qx[8], qy[8], qz[8];
    #pragma unroll
    for (int k = 0; k < 8; k++) {
        size_t idx = bb + p0 + k * 256 + tid;
        qx[k] = g_x[idx]; qy[k] = g_y[idx]; qz[k] = g_z[idx];
    }

    // phase 2: compute + ballot + store
    int cnt = 0;
    #pragma unroll
    for (int k = 0; k < 8; k++) {
        int p = p0 + k * 256 + tid;
        float m = 1e10f;
        #pragma unroll
        for (int t = 0; t < 4; t++) {
            float dx = qx[k] - sc[t].x, dy = qy[k] - sc[t].y, dz = qz[k] - sc[t].z;
            float d = dx * dx + dy * dy + dz * dz;
            m = fminf(m, d);
        }
        bool keep = (sqrtf(m) >= RADIUS);   // == (norm >= 0.2), sqrt monotone
        unsigned w = __ballot_sync(0xffffffffu, keep);
        if (lane == 0) g_bm[b * (NN / 32) + (p >> 5)] = w;
        cnt += keep;
    }
    #pragma unroll
    for (int off = 16; off; off >>= 1) cnt += __shfl_down_sync(0xffffffffu, cnt, off);
    if (lane == 0) s_c[warp] = cnt;
    __syncthreads();
    if (tid == 0) {
        int tot = 0;
        #pragma unroll
        for (int i = 0; i < 8; i++) tot += s_c[i];
        g_cnt[b * 32 + chunk] = tot;
    }
}

// ---------------------------------------------------------------------------
// K6: scatter kept points directly to out[rank]. grid (32, BB) x 256.
// Rank = batch-stable prefix (chunk offset + word prefix + bit prefix).
// ---------------------------------------------------------------------------
__global__ void __launch_bounds__(256) scatter_kernel(const float* __restrict__ pts,
                                                      float* __restrict__ out) {
    const int b = blockIdx.y, chunk = blockIdx.x, tid = threadIdx.x;
    __shared__ unsigned s_w[64];
    __shared__ int s_wpref[64];
    __shared__ int s_wtot[2];
    __shared__ int s_chunk_off;

    // warp 0: exclusive scan of the batch's 32 chunk counts
    if (tid < 32) {
        int v = g_cnt[b * 32 + tid];
        int inc = v;
        #pragma unroll
        for (int off = 1; off < 32; off <<= 1) {
            int n = __shfl_up_sync(0xffffffffu, inc, off);
            if (tid >= off) inc += n;
        }
        if (tid == chunk) s_chunk_off = inc - v;
        if (chunk == 0 && tid == 31) g_numvalid[b] = inc;
    }
    // load this chunk's 64 bitmask words
    if (tid >= 64 && tid < 128) s_w[tid - 64] = g_bm[b * (NN / 32) + chunk * 64 + (tid - 64)];
    __syncthreads();

    // exclusive word-prefix over 64 popcounts (warps 0,1)
    if (tid < 64) {
        int pc = __popc(s_w[tid]);
        int lane = tid & 31;
        int inc = pc;
        #pragma unroll
        for (int off = 1; off < 32; off <<= 1) {
            int n = __shfl_up_sync(0xffffffffu, inc, off);
            if (lane >= off) inc += n;
        }
        s_wpref[tid] = inc - pc;
        if (lane == 31) s_wtot[tid >> 5] = inc;
    }
    __syncthreads();
    if (tid >= 32 && tid < 64) s_wpref[tid] += s_wtot[0];
    __syncthreads();

    const float* __restrict__ base = pts + (size_t)b * NN * 6;
    float* __restrict__ obase = out + (size_t)b * NN * 6;
    const int p0 = chunk * 2048;
    #pragma unroll
    for (int k = 0; k < 8; k++) {
        int pl = k * 256 + tid;                 // local point 0..2047
        unsigned word = s_w[pl >> 5];
        int bit = pl & 31;
        if ((word >> bit) & 1u) {
            int rank = s_chunk_off + s_wpref[pl >> 5] + __popc(word & ((1u << bit) - 1u));
            const float2* s = (const float2*)(base + (size_t)(p0 + pl) * 6);
            float2 a0 = s[0], a1 = s[1], a2 = s[2];
            float2* o = (float2*)(obase + (size_t)rank * 6);
            o[0] = a0; o[1] = a1; o[2] = a2;
        }
    }
}

// ---------------------------------------------------------------------------
// K7: tail fill: rows j >= nv copy from out[j % nv]; nv==0 -> zeros.
// Source rows were written by K6 (previous kernel) — no hazard.
// ---------------------------------------------------------------------------
__global__ void __launch_bounds__(256) tail_kernel(float* __restrict__ out) {
    int i = blockIdx.x * blockDim.x + threadIdx.x;
    if (i >= BB * NN) return;
    int b = i >> 16;
    int j = i & (NN - 1);
    int nv = g_numvalid[b];
    float* __restrict__ obase = out + (size_t)b * NN * 6;
    if (nv == 0) {
        float2 z = make_float2(0.f, 0.f);
        float2* o = (float2*)(obase + (size_t)j * 6);
        o[0] = z; o[1] = z; o[2] = z;
        return;
    }
    if (j < nv) return;
    int k = j % nv;
    const float2* s = (const float2*)(obase + (size_t)k * 6);
    float2 a0 = s[0], a1 = s[1], a2 = s[2];
    float2* o = (float2*)(obase + (size_t)j * 6);
    o[0] = a0; o[1] = a1; o[2] = a2;
}

extern "C" void kernel_launch(void* const* d_in, const int* in_sizes, int n_in,
                              void* d_out, int out_size) {
    const float* pts = (const float*)d_in[0];
    float* out = (float*)d_out;
    (void)in_sizes; (void)n_in; (void)out_size;

    sweep1_pack_kernel<<<dim3(64, BB), 256>>>(pts);
    sweep_kernel<2><<<dim3(64, BB), 256>>>(pts);
    sweep_kernel<3><<<dim3(64, BB), 256>>>(pts);
    finalize_kernel<<<BB, 32>>>(pts);
    keep_kernel<<<dim3(32, BB), 256>>>();
    scatter_kernel<<<dim3(32, BB), 256>>>(pts, out);
    tail_kernel<<<(BB * NN + 255) / 256, 256>>>(out);
}